// round 9
// baseline (speedup 1.0000x reference)
#include <cuda_runtime.h>
#include <cuda_bf16.h>
#include <cstdint>

#define BB 128
#define TT 1024
#define DD 128
#define CC 384
#define TILE 64                   // rows per work CTA
#define NE_BLK 64                 // E-setup CTAs

// ---- smem byte offsets ----
#define S_MS 0                    // 512 B mean
#define S_E  512                  // 32 KB E (bf16, swizzled); aliased by Dbuf
#define S_A  (S_E + 34816)        // 16 KB  Ahi = bf16(V)  (Pt scratch alias, 4 KB)
#define S_AL (S_A + 16384)        // 16 KB  Alo = bf16(V - hi)
#define S_TOTAL (S_AL + 16384)    // 68096 B
#define DPAD 136                  // Dbuf row pitch in floats

// ---- device scratch (overwritten/reset every launch -> deterministic) ----
__device__ float g_partial[BB * 16 * DD];
__device__ __align__(16) unsigned char g_E[32768];
__device__ unsigned g_sync[256];  // [0..127] per-batch counters, [128] = E count

// swizzled offset inside a [rows][128] bf16 tile with 256B rows
__device__ __forceinline__ uint32_t tile_off(int r, int k) {
    return (uint32_t)r * 256u + ((((uint32_t)k >> 3) ^ ((uint32_t)r & 7u)) << 4)
         + ((uint32_t)k & 7u) * 2u;
}

__device__ __forceinline__ uint32_t smem_u32(const void* p) {
    uint32_t a;
    asm("{ .reg .u64 t; cvta.to.shared.u64 t, %1; cvt.u32.u64 %0, t; }"
        : "=r"(a) : "l"(p));
    return a;
}
__device__ __forceinline__ unsigned ld_acq(const unsigned* p) {
    unsigned v;
    asm volatile("ld.acquire.gpu.global.u32 %0, [%1];" : "=r"(v) : "l"(p) : "memory");
    return v;
}

#define LDMATRIX_X4(r0, r1, r2, r3, addr)                                      \
    asm volatile("ldmatrix.sync.aligned.m8n8.x4.shared.b16 {%0,%1,%2,%3}, [%4];" \
        : "=r"(r0), "=r"(r1), "=r"(r2), "=r"(r3) : "r"(addr))

#define MMA_BF16(d, a0, a1, a2, a3, b0, b1)                                    \
    asm volatile("mma.sync.aligned.m16n8k16.row.col.f32.bf16.bf16.f32 "        \
        "{%0,%1,%2,%3}, {%4,%5,%6,%7}, {%8,%9}, {%0,%1,%2,%3};"                \
        : "+f"((d)[0]), "+f"((d)[1]), "+f"((d)[2]), "+f"((d)[3])               \
        : "r"(a0), "r"(a1), "r"(a2), "r"(a3), "r"(b0), "r"(b1))

#define CP_ASYNC16(saddr, gaddr)                                               \
    asm volatile("cp.async.cg.shared.global [%0], [%1], 16;"                   \
        :: "r"(saddr), "l"(gaddr) : "memory")
#define CP_COMMIT() asm volatile("cp.async.commit_group;" ::: "memory")
#define CP_WAIT0()  asm volatile("cp.async.wait_group 0;" ::: "memory")

__device__ __forceinline__ float2 bfx2f(uint32_t u) {
    return __bfloat1622float2(*reinterpret_cast<__nv_bfloat162*>(&u));
}

// ---------------------------------------------------------------------------
// Single fused kernel. bids [0,64): E setup. bids [64, 64+2048): work CTAs.
// ---------------------------------------------------------------------------
__global__ __launch_bounds__(256, 2)
void crosschan_fused_kernel(const float* __restrict__ x,
                            const float* __restrict__ kern,
                            float* __restrict__ out)
{
    extern __shared__ char smem[];
    const uint32_t sbase = smem_u32(smem);
    const int tid = threadIdx.x;

    // ------------------------- E setup CTAs --------------------------
    if (blockIdx.x < NE_BLK) {
        int idx = blockIdx.x * 256 + tid;          // 16384 elements
        int n = idx >> 7, k = idx & 127;
        float v = kern[k * DD + n] - (n == k ? 1.0f : 0.0f);
        *(__nv_bfloat16*)(g_E + tile_off(n, k)) = __float2bfloat16(v);
        __threadfence();
        __syncthreads();
        if (tid == 0) atomicAdd(&g_sync[128], 1u);
        return;
    }

    const int wb   = blockIdx.x - NE_BLK;          // work id 0..2047
    const int b    = wb >> 4;                      // batch
    const int wid  = tid >> 5;
    const int lane = tid & 31;
    float* Ms = (float*)(smem + S_MS);
    float* Db = (float*)(smem + S_E);              // Dbuf aliases E after MMA
    float* Pt = (float*)(smem + S_A);              // col-sum scratch [8][128]

    // -------- hoist ALL phase-1 x loads at cycle 0 (128 KB/CTA) -------
    const int l  = tid & 7;                        // column group
    const int rr = tid >> 3;                       // row within 32-row chunk
    float4 y4h[2][4], w4h[2][4];
#pragma unroll
    for (int p = 0; p < 2; ++p) {
        const float4* xr = (const float4*)(x + ((size_t)(wb * TILE + p * 32 + rr)) * CC);
#pragma unroll
        for (int i = 0; i < 4; ++i) {
            y4h[p][i] = xr[l * 4 + i];
            w4h[p][i] = xr[32 + l * 4 + i];
        }
    }

    // ---- Phase A from registers: column sums of this CTA's 64 y-rows ----
    {
        float4 cs[4];
#pragma unroll
        for (int i = 0; i < 4; ++i)
            cs[i] = make_float4(y4h[0][i].x + y4h[1][i].x,
                                y4h[0][i].y + y4h[1][i].y,
                                y4h[0][i].z + y4h[1][i].z,
                                y4h[0][i].w + y4h[1][i].w);
        // reduce over the 4 rr-values in this warp that share column group l
        // (lanes l, l+8, l+16, l+24)
#pragma unroll
        for (int d = 8; d <= 16; d <<= 1) {
#pragma unroll
            for (int i = 0; i < 4; ++i) {
                cs[i].x += __shfl_xor_sync(0xffffffffu, cs[i].x, d);
                cs[i].y += __shfl_xor_sync(0xffffffffu, cs[i].y, d);
                cs[i].z += __shfl_xor_sync(0xffffffffu, cs[i].z, d);
                cs[i].w += __shfl_xor_sync(0xffffffffu, cs[i].w, d);
            }
        }
        if (lane < 8) {
#pragma unroll
            for (int i = 0; i < 4; ++i)
                ((float4*)Pt)[wid * 32 + lane * 4 + i] = cs[i];
        }
    }
    __syncthreads();
    if (tid < 128) {
        float m = 0.f;
#pragma unroll
        for (int w = 0; w < 8; ++w) m += Pt[w * 128 + tid];
        g_partial[wb * DD + tid] = m;
    }
    __threadfence();
    __syncthreads();
    if (tid == 0) atomicAdd(&g_sync[b], 1u);

    // ---------------- spin E ready, start E copy, spin batch ----------
    if (tid == 0)
        while (ld_acq(&g_sync[128]) < (unsigned)NE_BLK) __nanosleep(64);
    __syncthreads();
    {
        const char* eg = (const char*)g_E;
#pragma unroll
        for (int i = 0; i < 8; ++i) {
            uint32_t off = (uint32_t)(tid + i * 256) * 16u;
            CP_ASYNC16(sbase + S_E + off, eg + off);
        }
        CP_COMMIT();
    }
    if (tid == 0)
        while (ld_acq(&g_sync[b]) < 16u) __nanosleep(64);
    __syncthreads();

    // mean reduce (128 threads, L2-hot partials)
    if (tid < DD) {
        float m = 0.f;
#pragma unroll
        for (int s = 0; s < 16; ++s) m += g_partial[(b * 16 + s) * DD + tid];
        Ms[tid] = m * (1.0f / (float)TT);
    }
    __syncthreads();

    // ------------------------------------------------------------------
    // Phase 1: softmax + intensity + V as bf16 hi/lo tiles (data in regs)
    // ------------------------------------------------------------------
#pragma unroll
    for (int p = 0; p < 2; ++p) {
        const int r = p * 32 + rr;
        const size_t rowbase = ((size_t)(wb * TILE + r)) * CC;
        float4* o4 = (float4*)(out + rowbase);

        float ex[16], s = 0.f;
#pragma unroll
        for (int i = 0; i < 4; ++i) {
            ex[4*i+0] = __expf(w4h[p][i].x); ex[4*i+1] = __expf(w4h[p][i].y);
            ex[4*i+2] = __expf(w4h[p][i].z); ex[4*i+3] = __expf(w4h[p][i].w);
            s += ex[4*i+0] + ex[4*i+1] + ex[4*i+2] + ex[4*i+3];
        }
        s += __shfl_xor_sync(0xffffffffu, s, 1);
        s += __shfl_xor_sync(0xffffffffu, s, 2);
        s += __shfl_xor_sync(0xffffffffu, s, 4);
        const float inv = 1.0f / s;

#pragma unroll
        for (int h = 0; h < 2; ++h) {
            float v[8];
#pragma unroll
            for (int i = 0; i < 2; ++i) {
                const int ii = h * 2 + i;
                const int c0 = l * 16 + ii * 4;
                float4 ev = make_float4(ex[4*ii+0], ex[4*ii+1],
                                        ex[4*ii+2], ex[4*ii+3]);
                o4[32 + l * 4 + ii] = ev;          // intensity = exp(w)
                v[4*i+0] = ev.x * inv * (y4h[p][ii].x - Ms[c0 + 0]);
                v[4*i+1] = ev.y * inv * (y4h[p][ii].y - Ms[c0 + 1]);
                v[4*i+2] = ev.z * inv * (y4h[p][ii].z - Ms[c0 + 2]);
                v[4*i+3] = ev.w * inv * (y4h[p][ii].w - Ms[c0 + 3]);
            }
            uint32_t ph[4], pl[4];
#pragma unroll
            for (int j = 0; j < 4; ++j) {
                float a = v[2*j], c = v[2*j+1];
                __nv_bfloat162 th = __floats2bfloat162_rn(a, c);
                float2 back = __bfloat1622float2(th);
                __nv_bfloat162 tl = __floats2bfloat162_rn(a - back.x, c - back.y);
                ph[j] = *reinterpret_cast<uint32_t*>(&th);
                pl[j] = *reinterpret_cast<uint32_t*>(&tl);
            }
            uint32_t off = tile_off(r, l * 16 + h * 8);
            *(uint4*)(smem + S_A  + off) = make_uint4(ph[0], ph[1], ph[2], ph[3]);
            *(uint4*)(smem + S_AL + off) = make_uint4(pl[0], pl[1], pl[2], pl[3]);
        }
    }
    CP_WAIT0();
    __syncthreads();

    // ------------------------------------------------------------------
    // Prefetch y_obs for the epilogue (lands during MMA + fold)
    // ------------------------------------------------------------------
    float4 yo[8];
#pragma unroll
    for (int it = 0; it < 8; ++it) {
        const int r = it * 8 + wid;
        const size_t base = ((size_t)(wb * TILE + r)) * CC;
        yo[it] = ((const float4*)(x + base + 2 * DD))[lane];
    }

    // ------------------------------------------------------------------
    // Phase 2: V@E via bf16 mma.sync (A hi from smem, E from smem)
    // ------------------------------------------------------------------
    const int m0 = (wid >> 1) * 16;
    const int nb = (wid & 1) * 64;

    float acc[8][4];
#pragma unroll
    for (int i = 0; i < 8; ++i)
#pragma unroll
        for (int j = 0; j < 4; ++j) acc[i][j] = 0.f;

    const int aRow = m0 + (lane & 7) + (lane & 8);
    const uint32_t aBase = sbase + S_A + aRow * 256;
    const uint32_t aXor  = (uint32_t)(aRow & 7) << 4;
    const uint32_t aSel  = (uint32_t)(lane >> 4);
    const int bRowOff = (lane & 7) + ((lane >> 4) << 3);
    const uint32_t bSel = (uint32_t)((lane >> 3) & 1);

#pragma unroll
    for (int ks = 0; ks < 8; ++ks) {
        uint32_t a0, a1, a2, a3;
        LDMATRIX_X4(a0, a1, a2, a3,
                    aBase + ((((2u * ks + aSel) << 4) ^ aXor)));
#pragma unroll
        for (int nt2 = 0; nt2 < 4; ++nt2) {
            const int n0 = nb + nt2 * 16;
            const int bRow = n0 + bRowOff;
            uint32_t baddr = sbase + S_E + bRow * 256
                           + ((((2u * ks + bSel) << 4) ^ ((uint32_t)(bRow & 7) << 4)));
            uint32_t b0, b1, b2, b3;
            LDMATRIX_X4(b0, b1, b2, b3, baddr);
            MMA_BF16(acc[nt2 * 2],     a0, a1, a2, a3, b0, b1);
            MMA_BF16(acc[nt2 * 2 + 1], a0, a1, a2, a3, b2, b3);
        }
    }
    __syncthreads();   // all warps done reading E before Dbuf overwrites it

    // ------------------------------------------------------------------
    // Phase 3a: fold D = acc + (hi+lo) + mean into Dbuf (aliases E)
    // ------------------------------------------------------------------
    {
        const int r1 = m0 + (lane >> 2);
        const int r2 = r1 + 8;
        const int cl = 2 * (lane & 3);
#pragma unroll
        for (int nt = 0; nt < 8; ++nt) {
            const int c = nb + nt * 8 + cl;
            const float m0c = Ms[c], m1c = Ms[c + 1];
            uint32_t o1 = tile_off(r1, c), o2 = tile_off(r2, c);
            float2 h1 = bfx2f(*(uint32_t*)(smem + S_A  + o1));
            float2 l1 = bfx2f(*(uint32_t*)(smem + S_AL + o1));
            float2 h2 = bfx2f(*(uint32_t*)(smem + S_A  + o2));
            float2 l2 = bfx2f(*(uint32_t*)(smem + S_AL + o2));
            *(float2*)&Db[r1 * DPAD + c] =
                make_float2(acc[nt][0] + h1.x + l1.x + m0c,
                            acc[nt][1] + h1.y + l1.y + m1c);
            *(float2*)&Db[r2 * DPAD + c] =
                make_float2(acc[nt][2] + h2.x + l2.x + m0c,
                            acc[nt][3] + h2.y + l2.y + m1c);
        }
    }
    __syncthreads();

    // ------------------------------------------------------------------
    // Phase 3b: coalesced epilogue: smooth = D; y_trans = y_obs - smooth
    // ------------------------------------------------------------------
    {
        const int J = lane;
#pragma unroll
        for (int it = 0; it < 8; ++it) {
            const int r = it * 8 + wid;
            float4 d4 = *(const float4*)&Db[r * DPAD + J * 4];
            const size_t base = ((size_t)(wb * TILE + r)) * CC;
            ((float4*)(out + base))[J] = d4;                      // smooth
            ((float4*)(out + base + 2 * DD))[J] =
                make_float4(yo[it].x - d4.x, yo[it].y - d4.y,
                            yo[it].z - d4.z, yo[it].w - d4.w);
        }
    }
}

// ---------------------------------------------------------------------------
extern "C" void kernel_launch(void* const* d_in, const int* in_sizes, int n_in,
                              void* d_out, int out_size) {
    const float* x    = (const float*)d_in[0];
    const float* kern = (const float*)d_in[1];
    float* out        = (float*)d_out;

    void* syncp = nullptr;
    cudaGetSymbolAddress(&syncp, g_sync);
    cudaMemsetAsync(syncp, 0, 256 * sizeof(unsigned), 0);

    cudaFuncSetAttribute(crosschan_fused_kernel,
                         cudaFuncAttributeMaxDynamicSharedMemorySize, S_TOTAL);
    crosschan_fused_kernel<<<NE_BLK + BB * (TT / TILE), 256, S_TOTAL>>>(x, kern, out);
}

// round 16
// speedup vs baseline: 1.0016x; 1.0016x over previous
#include <cuda_runtime.h>
#include <cuda_bf16.h>
#include <cstdint>

#define BB 128
#define TT 1024
#define DD 128
#define CC 384

// ---- smem layout (bytes) ----
#define S_MS   0                    // 512 B mean
#define S_E    1024                 // 32 KB E bf16 swizzled (persists)
#define S_A    33792                // 16 KB Ahi    (aliased by Pt during mean)
#define S_PT   33792
#define S_AL   50176                // 16 KB Alo
#define S_YW   66560                // 2 x 65 KB yw double buffer
#define YWSTR  66560
#define S_TOTAL (S_YW + 2 * YWSTR)  // 199680 B

#define PITCH_YW 260                // floats/row (256 + 4 pad)
#define PITCH_M  132                // floats/row (128 + 4 pad)
#define DPAD 136

// swizzled offset inside a [rows][128] bf16 tile with 256B rows
__device__ __forceinline__ uint32_t tile_off(int r, int k) {
    return (uint32_t)r * 256u + ((((uint32_t)k >> 3) ^ ((uint32_t)r & 7u)) << 4)
         + ((uint32_t)k & 7u) * 2u;
}
__device__ __forceinline__ uint32_t smem_u32(const void* p) {
    uint32_t a;
    asm("{ .reg .u64 t; cvta.to.shared.u64 t, %1; cvt.u32.u64 %0, t; }"
        : "=r"(a) : "l"(p));
    return a;
}

#define LDMATRIX_X4(r0, r1, r2, r3, addr)                                      \
    asm volatile("ldmatrix.sync.aligned.m8n8.x4.shared.b16 {%0,%1,%2,%3}, [%4];" \
        : "=r"(r0), "=r"(r1), "=r"(r2), "=r"(r3) : "r"(addr))

#define MMA_BF16(d, a0, a1, a2, a3, b0, b1)                                    \
    asm volatile("mma.sync.aligned.m16n8k16.row.col.f32.bf16.bf16.f32 "        \
        "{%0,%1,%2,%3}, {%4,%5,%6,%7}, {%8,%9}, {%0,%1,%2,%3};"                \
        : "+f"((d)[0]), "+f"((d)[1]), "+f"((d)[2]), "+f"((d)[3])               \
        : "r"(a0), "r"(a1), "r"(a2), "r"(a3), "r"(b0), "r"(b1))

#define CP_ASYNC16(saddr, gaddr)                                               \
    asm volatile("cp.async.cg.shared.global [%0], [%1], 16;"                   \
        :: "r"(saddr), "l"(gaddr) : "memory")
#define CP_COMMIT() asm volatile("cp.async.commit_group;" ::: "memory")
#define CP_WAIT0()  asm volatile("cp.async.wait_group 0;" ::: "memory")
#define CP_WAIT1()  asm volatile("cp.async.wait_group 1;" ::: "memory")

__device__ __forceinline__ float2 bfx2f(uint32_t u) {
    return __bfloat1622float2(*reinterpret_cast<__nv_bfloat162*>(&u));
}

// 64 rows x 256 floats (y+w) -> smem, pitch PITCH_YW. 16 x 16B per thread.
__device__ __forceinline__ void issue_yw_tile(uint32_t dst, const float* src, int tid) {
#pragma unroll
    for (int ii = 0; ii < 16; ++ii) {
        int idx = ii * 256 + tid;          // 0..4095
        int row = idx >> 6, seg = idx & 63;
        CP_ASYNC16(dst + (uint32_t)row * (PITCH_YW * 4) + (uint32_t)seg * 16,
                   (const char*)src + (size_t)row * (CC * 4) + (size_t)seg * 16);
    }
    CP_COMMIT();
}
// 64 rows x 128 floats (y only) -> smem, pitch PITCH_M. 8 x 16B per thread.
__device__ __forceinline__ void issue_y_tile(uint32_t dst, const float* src, int tid) {
#pragma unroll
    for (int ii = 0; ii < 8; ++ii) {
        int idx = ii * 256 + tid;          // 0..2047
        int row = idx >> 5, seg = idx & 31;
        CP_ASYNC16(dst + (uint32_t)row * (PITCH_M * 4) + (uint32_t)seg * 16,
                   (const char*)src + (size_t)row * (CC * 4) + (size_t)seg * 16);
    }
    CP_COMMIT();
}

// ---------------------------------------------------------------------------
// One persistent CTA per batch. 256 threads, ~195 KB smem, no global sync.
// ---------------------------------------------------------------------------
__global__ __launch_bounds__(256, 1)
void crosschan_batch_kernel(const float* __restrict__ x,
                            const float* __restrict__ kern,
                            float* __restrict__ out)
{
    extern __shared__ char smem[];
    const uint32_t sbase = smem_u32(smem);
    const int tid  = threadIdx.x;
    const int wid  = tid >> 5;
    const int lane = tid & 31;
    const int b    = blockIdx.x;
    const int l    = tid & 7;          // column group (8 per row)
    const int rr   = tid >> 3;         // row 0..31 within half-chunk
    float* Ms = (float*)(smem + S_MS);

    // ---------------- mean pipeline prologue: issue chunks 0,1 ----------
    issue_y_tile(sbase + S_YW,         x + ((size_t)(b * TT +  0)) * CC, tid);
    issue_y_tile(sbase + S_YW + YWSTR, x + ((size_t)(b * TT + 64)) * CC, tid);

    // ---------------- E setup in smem (overlaps mean cp.asyncs) ---------
    {
        const int n = tid & 127;
        const int khalf = tid >> 7;
#pragma unroll
        for (int c = 0; c < 8; ++c) {
            const int k0 = khalf * 64 + c * 8;
            uint32_t pk[4];
#pragma unroll
            for (int j2 = 0; j2 < 4; ++j2) {
                int ka = k0 + 2 * j2, kb = ka + 1;
                float va = kern[ka * DD + n] - (n == ka ? 1.0f : 0.0f);
                float vb = kern[kb * DD + n] - (n == kb ? 1.0f : 0.0f);
                __nv_bfloat162 t = __floats2bfloat162_rn(va, vb);
                pk[j2] = *reinterpret_cast<uint32_t*>(&t);
            }
            *(uint4*)(smem + S_E + tile_off(n, k0)) =
                make_uint4(pk[0], pk[1], pk[2], pk[3]);
        }
    }

    // ---------------- mean pass: 16 chunks, double buffered -------------
    float4 macc[4];
#pragma unroll
    for (int i = 0; i < 4; ++i) macc[i] = make_float4(0.f, 0.f, 0.f, 0.f);

    for (int ch = 0; ch < 16; ++ch) {
        if (ch < 15) CP_WAIT1(); else CP_WAIT0();
        __syncthreads();
        const float* bm = (const float*)(smem + S_YW + (ch & 1) * YWSTR);
#pragma unroll
        for (int p = 0; p < 2; ++p) {
            const int r = p * 32 + rr;
#pragma unroll
            for (int i = 0; i < 4; ++i) {
                float4 t = *(const float4*)(bm + r * PITCH_M + i * 32 + l * 4);
                macc[i].x += t.x; macc[i].y += t.y;
                macc[i].z += t.z; macc[i].w += t.w;
            }
        }
        __syncthreads();
        if (ch + 2 < 16)
            issue_y_tile(sbase + S_YW + (ch & 1) * YWSTR,
                         x + ((size_t)(b * TT + (ch + 2) * 64)) * CC, tid);
    }
    // reduce across the 4 rr-values in each warp (lanes xor 8, 16)
#pragma unroll
    for (int i = 0; i < 4; ++i) {
#pragma unroll
        for (int d = 8; d <= 16; d <<= 1) {
            macc[i].x += __shfl_xor_sync(0xffffffffu, macc[i].x, d);
            macc[i].y += __shfl_xor_sync(0xffffffffu, macc[i].y, d);
            macc[i].z += __shfl_xor_sync(0xffffffffu, macc[i].z, d);
            macc[i].w += __shfl_xor_sync(0xffffffffu, macc[i].w, d);
        }
    }
    if (lane < 8) {
        float4* pt = (float4*)(smem + S_PT);
#pragma unroll
        for (int i = 0; i < 4; ++i)
            pt[wid * 32 + i * 8 + lane] = macc[i];
    }
    __syncthreads();
    if (tid < DD) {
        const float* pt = (const float*)(smem + S_PT);
        float m = 0.f;
#pragma unroll
        for (int w = 0; w < 8; ++w) m += pt[w * 128 + tid];
        Ms[tid] = m * (1.0f / (float)TT);
    }
    __syncthreads();

    // ---------------- main pipeline prologue: issue yw 0,1 ---------------
    issue_yw_tile(sbase + S_YW,         x + ((size_t)(b * TT +  0)) * CC, tid);
    issue_yw_tile(sbase + S_YW + YWSTR, x + ((size_t)(b * TT + 64)) * CC, tid);

    // MMA per-lane constants
    const int m0 = (wid >> 1) * 16;
    const int nb = (wid & 1) * 64;
    const int aRow = m0 + (lane & 7) + (lane & 8);
    const uint32_t aBase = sbase + S_A + aRow * 256;
    const uint32_t aXor  = (uint32_t)(aRow & 7) << 4;
    const uint32_t aSel  = (uint32_t)(lane >> 4);
    const int bRowOff = (lane & 7) + ((lane >> 4) << 3);
    const uint32_t bSel = (uint32_t)((lane >> 3) & 1);

    // ---------------- main pass: 16 subtiles, double buffered ------------
    for (int ch = 0; ch < 16; ++ch) {
        if (ch < 15) CP_WAIT1(); else CP_WAIT0();
        __syncthreads();
        const float* bw = (const float*)(smem + S_YW + (ch & 1) * YWSTR);

        // ---- phase 1: softmax + intensity + A hi/lo tiles ----
#pragma unroll
        for (int p = 0; p < 2; ++p) {
            const int r = p * 32 + rr;
            const size_t rowbase = ((size_t)(b * TT + ch * 64 + r)) * CC;
            float4 y4[4], w4[4], ms4[4];
#pragma unroll
            for (int i = 0; i < 4; ++i) {
                y4[i]  = *(const float4*)(bw + r * PITCH_YW + i * 32 + l * 4);
                w4[i]  = *(const float4*)(bw + r * PITCH_YW + 128 + i * 32 + l * 4);
                ms4[i] = *(const float4*)(Ms + i * 32 + l * 4);
            }
            float ex[16], s = 0.f;
#pragma unroll
            for (int i = 0; i < 4; ++i) {
                ex[4*i+0] = __expf(w4[i].x); ex[4*i+1] = __expf(w4[i].y);
                ex[4*i+2] = __expf(w4[i].z); ex[4*i+3] = __expf(w4[i].w);
                s += ex[4*i+0] + ex[4*i+1] + ex[4*i+2] + ex[4*i+3];
            }
            s += __shfl_xor_sync(0xffffffffu, s, 1);
            s += __shfl_xor_sync(0xffffffffu, s, 2);
            s += __shfl_xor_sync(0xffffffffu, s, 4);
            const float inv = 1.0f / s;
#pragma unroll
            for (int i = 0; i < 4; ++i) {
                float4 ev = make_float4(ex[4*i+0], ex[4*i+1], ex[4*i+2], ex[4*i+3]);
                *(float4*)(out + rowbase + 128 + i * 32 + l * 4) = ev;  // intensity
                float v0 = ev.x * inv * (y4[i].x - ms4[i].x);
                float v1 = ev.y * inv * (y4[i].y - ms4[i].y);
                float v2 = ev.z * inv * (y4[i].z - ms4[i].z);
                float v3 = ev.w * inv * (y4[i].w - ms4[i].w);
                __nv_bfloat162 h01 = __floats2bfloat162_rn(v0, v1);
                __nv_bfloat162 h23 = __floats2bfloat162_rn(v2, v3);
                float2 b01 = __bfloat1622float2(h01);
                float2 b23 = __bfloat1622float2(h23);
                __nv_bfloat162 l01 = __floats2bfloat162_rn(v0 - b01.x, v1 - b01.y);
                __nv_bfloat162 l23 = __floats2bfloat162_rn(v2 - b23.x, v3 - b23.y);
                uint32_t off = tile_off(r, i * 32 + l * 4);
                *(uint2*)(smem + S_A  + off) =
                    make_uint2(*reinterpret_cast<uint32_t*>(&h01),
                               *reinterpret_cast<uint32_t*>(&h23));
                *(uint2*)(smem + S_AL + off) =
                    make_uint2(*reinterpret_cast<uint32_t*>(&l01),
                               *reinterpret_cast<uint32_t*>(&l23));
            }
        }
        __syncthreads();   // A tiles ready; yw[ch&1] dead

        // ---- prefetch y_obs (overlaps MMA) ----
        float4 yo[8];
#pragma unroll
        for (int it = 0; it < 8; ++it) {
            const size_t base = ((size_t)(b * TT + ch * 64 + it * 8 + wid)) * CC;
            yo[it] = ((const float4*)(x + base + 2 * DD))[lane];
        }

        // ---- MMA: V@E ----
        float acc[8][4];
#pragma unroll
        for (int i = 0; i < 8; ++i)
#pragma unroll
            for (int j = 0; j < 4; ++j) acc[i][j] = 0.f;

#pragma unroll
        for (int ks = 0; ks < 8; ++ks) {
            uint32_t a0, a1, a2, a3;
            LDMATRIX_X4(a0, a1, a2, a3,
                        aBase + ((((2u * ks + aSel) << 4) ^ aXor)));
#pragma unroll
            for (int nt2 = 0; nt2 < 4; ++nt2) {
                const int bRow = nb + nt2 * 16 + bRowOff;
                uint32_t baddr = sbase + S_E + bRow * 256
                               + ((((2u * ks + bSel) << 4) ^ ((uint32_t)(bRow & 7) << 4)));
                uint32_t b0, b1, b2, b3;
                LDMATRIX_X4(b0, b1, b2, b3, baddr);
                MMA_BF16(acc[nt2 * 2],     a0, a1, a2, a3, b0, b1);
                MMA_BF16(acc[nt2 * 2 + 1], a0, a1, a2, a3, b2, b3);
            }
        }

        // ---- fold into Dbuf (aliases dead yw[ch&1]) ----
        float* Db = (float*)(smem + S_YW + (ch & 1) * YWSTR);
        {
            const int r1 = m0 + (lane >> 2);
            const int r2 = r1 + 8;
            const int cl = 2 * (lane & 3);
#pragma unroll
            for (int nt = 0; nt < 8; ++nt) {
                const int c = nb + nt * 8 + cl;
                const float m0c = Ms[c], m1c = Ms[c + 1];
                uint32_t o1 = tile_off(r1, c), o2 = tile_off(r2, c);
                float2 h1 = bfx2f(*(uint32_t*)(smem + S_A  + o1));
                float2 l1 = bfx2f(*(uint32_t*)(smem + S_AL + o1));
                float2 h2 = bfx2f(*(uint32_t*)(smem + S_A  + o2));
                float2 l2 = bfx2f(*(uint32_t*)(smem + S_AL + o2));
                *(float2*)&Db[r1 * DPAD + c] =
                    make_float2(acc[nt][0] + h1.x + l1.x + m0c,
                                acc[nt][1] + h1.y + l1.y + m1c);
                *(float2*)&Db[r2 * DPAD + c] =
                    make_float2(acc[nt][2] + h2.x + l2.x + m0c,
                                acc[nt][3] + h2.y + l2.y + m1c);
            }
        }
        __syncthreads();

        // ---- epilogue: smooth + y_trans (coalesced) ----
#pragma unroll
        for (int it = 0; it < 8; ++it) {
            const int r = it * 8 + wid;
            float4 d4 = *(const float4*)&Db[r * DPAD + lane * 4];
            const size_t base = ((size_t)(b * TT + ch * 64 + r)) * CC;
            ((float4*)(out + base))[lane] = d4;
            ((float4*)(out + base + 2 * DD))[lane] =
                make_float4(yo[it].x - d4.x, yo[it].y - d4.y,
                            yo[it].z - d4.z, yo[it].w - d4.w);
        }
        __syncthreads();   // Db reads done before reissuing into this buffer

        // ---- issue yw[ch+2] into the freed buffer ----
        if (ch + 2 < 16)
            issue_yw_tile(sbase + S_YW + (ch & 1) * YWSTR,
                          x + ((size_t)(b * TT + (ch + 2) * 64)) * CC, tid);
    }
}

// ---------------------------------------------------------------------------
extern "C" void kernel_launch(void* const* d_in, const int* in_sizes, int n_in,
                              void* d_out, int out_size) {
    const float* x    = (const float*)d_in[0];
    const float* kern = (const float*)d_in[1];
    float* out        = (float*)d_out;

    cudaFuncSetAttribute(crosschan_batch_kernel,
                         cudaFuncAttributeMaxDynamicSharedMemorySize, S_TOTAL);
    crosschan_batch_kernel<<<BB, 256, S_TOTAL>>>(x, kern, out);
}